// round 8
// baseline (speedup 1.0000x reference)
#include <cuda_runtime.h>

// SparseTopKLayer: out = x + ((x*rms)*w)*mask*gamma
//   rms = rsqrt(mean(x^2)+1e-6); mask = |x_norm| >= kth_largest(|x_norm|, k)
// Rank on |x*w| (rms>0 row-constant -> identical ordering).
// One CTA per row, 512 threads, 4 elems/thread (low regs -> high occupancy).
// Gaussian-quantile window + adaptive histogram select; exact for arbitrary
// data via re-windowing. Minimal L1 traffic: x,w loaded once, g in epilogue.

constexpr int D    = 2048;
constexpr int T    = 512;
constexpr int W    = T / 32;     // 16 warps
constexpr int BINS = 128;

__device__ __forceinline__ float inv_phi_tail(float q) {
    // Phi^{-1}(1-q), q in (0,0.5]; Abramowitz-Stegun 26.2.23, |err|<4.5e-4
    q = fminf(fmaxf(q, 1e-7f), 0.4999f);
    float s = sqrtf(-2.0f * __logf(q));
    return s - (2.30753f + 0.27061f * s) / (1.0f + s * (0.99229f + 0.04481f * s));
}

__global__ void __launch_bounds__(T, 4) sparse_topk_kernel(
    const float* __restrict__ x,
    const float* __restrict__ w,
    const float* __restrict__ g,
    const int* __restrict__ kptr,
    float* __restrict__ out)
{
    const int row  = blockIdx.x;
    const int t    = threadIdx.x;
    const int lane = t & 31;
    const int wid  = t >> 5;

    __shared__ float2   red[W];
    __shared__ __align__(16) unsigned hist[2][BINS];
    __shared__ unsigned lo_sh, hi_sh, thr_sh, thrmin_sh, thrmax_sh, above_sh;
    __shared__ int      r_sh, mode_sh;
    __shared__ float    rms_sh;

    // ---- load x,w once; 4 elems/thread; dual sums ----
    const float4* xr = reinterpret_cast<const float4*>(x) + (size_t)row * (D / 4);
    const float4* wv = reinterpret_cast<const float4*>(w);
    float4 xa = xr[t];
    float4 wa = wv[t];
    float xv[4] = {xa.x, xa.y, xa.z, xa.w};
    float xw[4];
    float ss = 0.0f, sw = 0.0f;
    {
        float wf[4] = {wa.x, wa.y, wa.z, wa.w};
        #pragma unroll
        for (int i = 0; i < 4; i++) {
            xw[i] = xv[i] * wf[i];
            ss = fmaf(xv[i], xv[i], ss);
            sw = fmaf(xw[i], xw[i], sw);
        }
    }
    #pragma unroll
    for (int o = 16; o > 0; o >>= 1) {
        ss += __shfl_xor_sync(0xffffffffu, ss, o);
        sw += __shfl_xor_sync(0xffffffffu, sw, o);
    }
    if (lane == 0) red[wid] = make_float2(ss, sw);
    if (t < 2 * BINS) ((unsigned*)hist)[t] = 0u;      // zero both buffers
    if (t == 0) { above_sh = 0u; thrmin_sh = 0xFFFFFFFFu; thrmax_sh = 0u; }
    __syncthreads();

    // ---- warp0: rms + Gaussian-quantile window ----
    if (t < W) {
        float2 v = red[t];
        #pragma unroll
        for (int o = W / 2; o > 0; o >>= 1) {
            v.x += __shfl_xor_sync(0xffffu, v.x, o);
            v.y += __shfl_xor_sync(0xffffu, v.y, o);
        }
        if (t == 0) {
            rms_sh = rsqrtf(v.x * (1.0f / (float)D) + 1e-6f);
            float sigma = sqrtf(v.y * (1.0f / (float)D));
            int k = *kptr;
            float t1 = inv_phi_tail((float)(k + 64) * (0.5f / (float)D));
            float t2 = inv_phi_tail((float)(k - 64 > 1 ? k - 64 : 1) * (0.5f / (float)D));
            unsigned b1 = (t1 > 0.0f) ? __float_as_uint(t1 * sigma) : 0u;
            unsigned b2 = __float_as_uint(fmaxf(t2, 0.0f) * sigma);
            if (b2 <= b1) b2 = b1 + 1u;
            lo_sh = b1; hi_sh = b2; r_sh = k; mode_sh = 0;
        }
    }
    __syncthreads();

    // ---- adaptive-window histogram select (exact) ----
    unsigned thr = 0u;
    int p = 0, rnd = 0;
    while (true) {
        const unsigned lo = lo_sh, hi = hi_sh;
        const unsigned range = hi - lo;
        const int s = (range > (unsigned)BINS) ? (25 - __clz(range - 1u)) : 0;
        unsigned* h = hist[p];
        unsigned above = 0u;
        #pragma unroll
        for (int i = 0; i < 4; i++) {
            unsigned ub = __float_as_uint(xw[i]) & 0x7FFFFFFFu;
            unsigned d = ub - lo;
            if (d < range) atomicAdd(&h[d >> s], 1u);
            if (rnd == 0) above += (ub >= hi);
        }
        if (rnd == 0) {
            above = __reduce_add_sync(0xffffffffu, above);
            if (lane == 0) atomicAdd(&above_sh, above);
        }
        if (t < BINS) hist[p ^ 1][t] = 0u;            // prep next buffer
        __syncthreads();

        if (t < 32) {   // warp0: suffix scan + classify + publish
            uint4 hv = *reinterpret_cast<const uint4*>(&h[lane * 4]);
            unsigned hr[4] = {hv.x, hv.y, hv.z, hv.w};
            unsigned bs = hr[0] + hr[1] + hr[2] + hr[3];
            unsigned S = bs;
            #pragma unroll
            for (int o = 1; o < 32; o <<= 1) {
                unsigned v = __shfl_down_sync(0xffffffffu, S, o);
                if (lane + o < 32) S += v;
            }
            unsigned total = __shfl_sync(0xffffffffu, S, 0);
            int r = r_sh;
            if (rnd == 0) r -= (int)above_sh;

            if (r <= 0) {                       // threshold above window
                if (lane == 0) { lo_sh = hi; hi_sh = 0x80000000u;
                                 r_sh = r + (int)above_sh; mode_sh = 0; }
            } else if ((unsigned)r > total) {   // threshold below window
                if (lane == 0) { hi_sh = lo; lo_sh = 0u;
                                 r_sh = r - (int)total; mode_sh = 0; }
            } else {
                unsigned suf = S - bs;          // count in strictly-higher lanes
                int bj = -1; unsigned cb = 0, abv = 0;
                #pragma unroll
                for (int j = 3; j >= 0; j--) {
                    unsigned ns = suf + hr[j];
                    if (suf < (unsigned)r && ns >= (unsigned)r) { bj = j; cb = hr[j]; abv = suf; }
                    suf = ns;
                }
                unsigned bal = __ballot_sync(0xffffffffu, bj >= 0);
                int src = __ffs(bal) - 1;
                unsigned B = __shfl_sync(0xffffffffu, (unsigned)(lane * 4 + bj), src);
                cb  = __shfl_sync(0xffffffffu, cb, src);
                abv = __shfl_sync(0xffffffffu, abv, src);
                if (lane == 0) {
                    int r2 = r - (int)abv;
                    unsigned nlo = lo + (B << s);
                    unsigned nhi = lo + ((B + 1u) << s);
                    if (nhi > hi) nhi = hi;
                    lo_sh = nlo; hi_sh = nhi; r_sh = r2;
                    if (s == 0)             { mode_sh = 1; thr_sh = nlo; }
                    else if ((int)cb == r2) { mode_sh = 2; }  // thr = min in bucket
                    else if (r2 == 1)       { mode_sh = 3; }  // thr = max in bucket
                    else                    { mode_sh = 0; }
                }
            }
        }
        __syncthreads();

        int m = mode_sh;
        if (m == 1) { thr = thr_sh; break; }
        if (m >= 2) {
            const unsigned nlo = lo_sh, nrange = hi_sh - lo_sh;
            if (m == 2) {
                unsigned lm = 0xFFFFFFFFu;
                #pragma unroll
                for (int i = 0; i < 4; i++) {
                    unsigned ub = __float_as_uint(xw[i]) & 0x7FFFFFFFu;
                    if (ub - nlo < nrange) lm = min(lm, ub);
                }
                lm = __reduce_min_sync(0xffffffffu, lm);
                if (lane == 0) atomicMin(&thrmin_sh, lm);
            } else {
                unsigned lm = 0u;
                #pragma unroll
                for (int i = 0; i < 4; i++) {
                    unsigned ub = __float_as_uint(xw[i]) & 0x7FFFFFFFu;
                    if (ub - nlo < nrange) lm = max(lm, ub);
                }
                lm = __reduce_max_sync(0xffffffffu, lm);
                if (lane == 0) atomicMax(&thrmax_sh, lm);
            }
            __syncthreads();
            thr = (m == 2) ? thrmin_sh : thrmax_sh;
            break;
        }
        p ^= 1; rnd++;
    }

    // ---- epilogue: out = x + (xw*rms)*g where |xw| >= thr ----
    const float4* gv = reinterpret_cast<const float4*>(g);
    float4 ga = gv[t];
    float gf[4] = {ga.x, ga.y, ga.z, ga.w};
    const float rms  = rms_sh;
    const float thrf = __uint_as_float(thr);

    float fo[4];
    #pragma unroll
    for (int i = 0; i < 4; i++) {
        float keep = (fabsf(xw[i]) >= thrf) ? (rms * gf[i]) : 0.0f;
        fo[i] = fmaf(xw[i], keep, xv[i]);
    }
    float4* orow = reinterpret_cast<float4*>(out) + (size_t)row * (D / 4);
    orow[t] = make_float4(fo[0], fo[1], fo[2], fo[3]);
}

extern "C" void kernel_launch(void* const* d_in, const int* in_sizes, int n_in,
                              void* d_out, int out_size)
{
    const float* x = (const float*)d_in[0];
    const float* w = (const float*)d_in[1];
    const float* g = (const float*)d_in[2];
    const int*   k = (const int*)d_in[3];

    int N = in_sizes[0] / D;   // 32768 rows
    sparse_topk_kernel<<<N, T>>>(x, w, g, k, (float*)d_out);
}

// round 9
// speedup vs baseline: 1.4689x; 1.4689x over previous
#include <cuda_runtime.h>

// SparseTopKLayer: out = x + ((x*rms)*w)*mask*gamma
//   rms = rsqrt(mean(x^2)+1e-6); mask = |x_norm| >= kth_largest(|x_norm|, k)
// Rank on |x*w| (rms>0 row-constant -> identical ordering).
// One CTA per row, 256 threads, 8 elems/thread in registers.
// Window sigma from mean(x^2) (exact when w==1; heuristic otherwise).
// Round-0 window is open-topped [lo, inf) with clamped tail bin (no separate
// above-count). Adaptive re-windowing keeps the threshold exact.

constexpr int D    = 2048;
constexpr int T    = 256;
constexpr int BINS = 128;

__device__ __forceinline__ float inv_phi_tail(float q) {
    q = fminf(fmaxf(q, 1e-7f), 0.4999f);
    float s = sqrtf(-2.0f * __logf(q));
    return s - (2.30753f + 0.27061f * s) / (1.0f + s * (0.99229f + 0.04481f * s));
}

__global__ void __launch_bounds__(T, 6) sparse_topk_kernel(
    const float* __restrict__ x,
    const float* __restrict__ w,
    const float* __restrict__ g,
    const int* __restrict__ kptr,
    float* __restrict__ out)
{
    const int row  = blockIdx.x;
    const int t    = threadIdx.x;
    const int lane = t & 31;
    const int wid  = t >> 5;

    __shared__ float    red[8];
    __shared__ __align__(16) unsigned hist[2][BINS];
    __shared__ unsigned lo_sh, hi_sh, thr_sh, thrmin_sh, thrmax_sh;
    __shared__ int      r_sh, s_sh, mode_sh;
    __shared__ float    rms_sh;

    // ---- load x,w once; xw in regs; single sum (x^2) ----
    const float4* xr = reinterpret_cast<const float4*>(x) + (size_t)row * (D / 4);
    const float4* wv = reinterpret_cast<const float4*>(w);
    float4 xa = xr[t], xb = xr[t + T];
    float4 wa = wv[t], wb = wv[t + T];

    float xv[8] = {xa.x,xa.y,xa.z,xa.w,xb.x,xb.y,xb.z,xb.w};
    float xw[8];
    float ss = 0.0f;
    {
        float wf[8] = {wa.x,wa.y,wa.z,wa.w,wb.x,wb.y,wb.z,wb.w};
        #pragma unroll
        for (int i = 0; i < 8; i++) {
            xw[i] = xv[i] * wf[i];
            ss = fmaf(xv[i], xv[i], ss);
        }
    }
    #pragma unroll
    for (int o = 16; o > 0; o >>= 1)
        ss += __shfl_xor_sync(0xffffffffu, ss, o);
    if (lane == 0) red[wid] = ss;
    ((unsigned*)hist)[t] = 0u;                 // zero both buffers
    if (t == 0) { thrmin_sh = 0xFFFFFFFFu; thrmax_sh = 0u; }
    __syncthreads();

    // ---- warp0: rms + quantile window ----
    if (t < 8) {
        float v = red[t];
        #pragma unroll
        for (int o = 4; o > 0; o >>= 1) v += __shfl_xor_sync(0xffu, v, o);
        if (t == 0) {
            float ms = v * (1.0f / (float)D);
            rms_sh = rsqrtf(ms + 1e-6f);
            float sigma = sqrtf(ms);            // assumes |w|~1 (heuristic only)
            int k = *kptr;
            float t1 = inv_phi_tail((float)(k + 96) * (0.5f / (float)D));
            float t2 = inv_phi_tail((float)(k - 96 > 1 ? k - 96 : 1) * (0.5f / (float)D));
            unsigned lo = (t1 > 0.0f) ? __float_as_uint(t1 * sigma) : 0u;
            unsigned hq = __float_as_uint(fmaxf(t2, 0.0f) * sigma);
            if (hq <= lo) hq = lo + 1u;
            unsigned wsoft = hq - lo;
            lo_sh = lo;
            hi_sh = 0x80000000u;                // open top: tail folds into bin 127
            s_sh  = (wsoft > (unsigned)BINS) ? (25 - __clz(wsoft - 1u)) : 0;
            r_sh  = k; mode_sh = 0;
        }
    }
    __syncthreads();

    // ---- adaptive-window histogram select (exact) ----
    unsigned thr = 0u;
    int p = 0;
    while (true) {
        const unsigned lo = lo_sh, hi = hi_sh;
        const unsigned range = hi - lo;
        const int s = s_sh;
        unsigned* h = hist[p];
        #pragma unroll
        for (int i = 0; i < 8; i++) {
            unsigned ub = __float_as_uint(xw[i]) & 0x7FFFFFFFu;
            unsigned d = ub - lo;
            if (d < range) {
                unsigned b = d >> s;
                if (b > (unsigned)(BINS - 1)) b = BINS - 1;    // tail bin
                atomicAdd(&h[b], 1u);
            }
        }
        if (t < BINS) hist[p ^ 1][t] = 0u;      // prep next buffer
        __syncthreads();

        if (t < 32) {   // warp0: suffix scan + classify + publish
            uint4 hv = *reinterpret_cast<const uint4*>(&h[lane * 4]);
            unsigned hr[4] = {hv.x, hv.y, hv.z, hv.w};
            unsigned bs = hr[0] + hr[1] + hr[2] + hr[3];
            unsigned S = bs;
            #pragma unroll
            for (int o = 1; o < 32; o <<= 1) {
                unsigned v = __shfl_down_sync(0xffffffffu, S, o);
                if (lane + o < 32) S += v;
            }
            unsigned total = __shfl_sync(0xffffffffu, S, 0);
            int r = r_sh;

            if ((unsigned)r > total) {           // threshold below window
                if (lane == 0) {
                    unsigned nrange = lo;        // new window [0, lo)
                    hi_sh = lo; lo_sh = 0u;
                    s_sh = (nrange > (unsigned)BINS) ? (25 - __clz(nrange - 1u)) : 0;
                    r_sh = r - (int)total; mode_sh = 0;
                }
            } else {
                unsigned suf = S - bs;           // count in strictly-higher lanes
                int bj = -1; unsigned cb = 0, abv = 0;
                #pragma unroll
                for (int j = 3; j >= 0; j--) {
                    unsigned ns = suf + hr[j];
                    if (suf < (unsigned)r && ns >= (unsigned)r) { bj = j; cb = hr[j]; abv = suf; }
                    suf = ns;
                }
                unsigned bal = __ballot_sync(0xffffffffu, bj >= 0);
                int src = __ffs(bal) - 1;
                unsigned B = __shfl_sync(0xffffffffu, (unsigned)(lane * 4 + bj), src);
                cb  = __shfl_sync(0xffffffffu, cb, src);
                abv = __shfl_sync(0xffffffffu, abv, src);
                if (lane == 0) {
                    int r2 = r - (int)abv;
                    unsigned nlo = lo + (B << s);
                    unsigned nhi = (B >= (unsigned)(BINS - 1)) ? hi : (lo + ((B + 1u) << s));
                    if (nhi > hi) nhi = hi;
                    unsigned nrange = nhi - nlo;
                    lo_sh = nlo; hi_sh = nhi; r_sh = r2;     // publish on ALL paths
                    if (nrange <= 1u)       { mode_sh = 1; thr_sh = nlo; }
                    else if ((int)cb == r2) { mode_sh = 2; } // thr = min in bucket
                    else if (r2 == 1)       { mode_sh = 3; } // thr = max in bucket
                    else {
                        mode_sh = 0;
                        s_sh = (nrange > (unsigned)BINS) ? (25 - __clz(nrange - 1u)) : 0;
                    }
                }
            }
        }
        __syncthreads();

        int m = mode_sh;
        if (m == 1) { thr = thr_sh; break; }
        if (m >= 2) {
            const unsigned nlo = lo_sh, nrange = hi_sh - lo_sh;   // bucket window
            if (m == 2) {
                unsigned lm = 0xFFFFFFFFu;
                #pragma unroll
                for (int i = 0; i < 8; i++) {
                    unsigned ub = __float_as_uint(xw[i]) & 0x7FFFFFFFu;
                    if (ub - nlo < nrange) lm = min(lm, ub);
                }
                lm = __reduce_min_sync(0xffffffffu, lm);
                if (lane == 0) atomicMin(&thrmin_sh, lm);
            } else {
                unsigned lm = 0u;
                #pragma unroll
                for (int i = 0; i < 8; i++) {
                    unsigned ub = __float_as_uint(xw[i]) & 0x7FFFFFFFu;
                    if (ub - nlo < nrange) lm = max(lm, ub);
                }
                lm = __reduce_max_sync(0xffffffffu, lm);
                if (lane == 0) atomicMax(&thrmax_sh, lm);
            }
            __syncthreads();
            thr = (m == 2) ? thrmin_sh : thrmax_sh;
            break;
        }
        p ^= 1;
    }

    // ---- epilogue: out = x + (xw*rms)*g where |xw| >= thr ----
    const float4* gv = reinterpret_cast<const float4*>(g);
    float4 ga = gv[t], gb = gv[t + T];
    float gf[8] = {ga.x,ga.y,ga.z,ga.w,gb.x,gb.y,gb.z,gb.w};
    const float rms  = rms_sh;
    const float thrf = __uint_as_float(thr);

    float fo[8];
    #pragma unroll
    for (int i = 0; i < 8; i++) {
        float keep = (fabsf(xw[i]) >= thrf) ? (rms * gf[i]) : 0.0f;
        fo[i] = fmaf(xw[i], keep, xv[i]);
    }
    float4* orow = reinterpret_cast<float4*>(out) + (size_t)row * (D / 4);
    orow[t]     = make_float4(fo[0], fo[1], fo[2], fo[3]);
    orow[t + T] = make_float4(fo[4], fo[5], fo[6], fo[7]);
}

extern "C" void kernel_launch(void* const* d_in, const int* in_sizes, int n_in,
                              void* d_out, int out_size)
{
    const float* x = (const float*)d_in[0];
    const float* w = (const float*)d_in[1];
    const float* g = (const float*)d_in[2];
    const int*   k = (const int*)d_in[3];

    int N = in_sizes[0] / D;   // 32768 rows
    sparse_topk_kernel<<<N, T>>>(x, w, g, k, (float*)d_out);
}